// round 3
// baseline (speedup 1.0000x reference)
#include <cuda_runtime.h>
#include <math.h>

#define HS   14
#define PX   196
#define SEQ  197
#define PW   16            // padded grid width
#define PSZ  256           // padded grid size (16x16)
#define BIGL 0x3FFFFFFF
#define WPB  8             // warps per block

__global__ __launch_bounds__(256) void blob_loss_kernel(
    const float* __restrict__ dot_qk,
    float* __restrict__ out,
    float inv_n, int ntask)
{
    __shared__ int   lab_s[WPB][PSZ];
    __shared__ float pu_s [WPB][PSZ];

    const int warp = threadIdx.x >> 5;
    const int lane = threadIdx.x & 31;
    const int bh   = blockIdx.x * WPB + warp;
    if (bh >= ntask) return;

    int*   LAB = lab_s[warp];
    float* PU  = pu_s [warp];

    const float* rowp = dot_qk + (size_t)bh * (SEQ * SEQ) + 1;

    // ---- load 196 contiguous floats (lane + 32k), compute padded indices
    float x[7];
    int   pp[7];
    float sum = 0.f;
    #pragma unroll
    for (int r = 0; r < 7; r++) {
        int p   = r * 32 + lane;
        bool ok = (p < PX);
        x[r] = ok ? rowp[p] : 0.f;
        sum += x[r];
        int ri = p / HS, ci = p - ri * HS;
        pp[r] = ok ? ((ri + 1) * PW + ci + 1) : -1;
    }
    #pragma unroll
    for (int o = 16; o; o >>= 1) sum += __shfl_xor_sync(0xffffffffu, sum, o);
    const float m = sum * (1.0f / 196.0f);

    // ---- init padded label grid (BIG border + background) and pu
    #pragma unroll
    for (int r = 0; r < 8; r++) {
        LAB[r * 32 + lane] = BIGL;
        PU [r * 32 + lane] = 0.f;
    }
    __syncwarp();

    // ---- mask, xv (registers), seed labels, B
    float xv[7];
    unsigned mk = 0;
    float Bsum = 0.f;
    #pragma unroll
    for (int r = 0; r < 7; r++) {
        xv[r] = 0.f;
        if (pp[r] >= 0) {
            xv[r] = fmaxf(x[r] - m, 0.f) + 1e-9f;
            if (x[r] > m) {
                mk |= (1u << r);
                Bsum += xv[r];
                LAB[pp[r]] = pp[r];
            }
        }
    }
    #pragma unroll
    for (int o = 16; o; o >>= 1) Bsum += __shfl_xor_sync(0xffffffffu, Bsum, o);
    __syncwarp();

    // ---- connected components: branchless 3x3 min + double pointer-jump,
    //      Jacobi iterations to exact fixpoint (warp-local sync only)
    for (;;) {
        int nl[7];
        #pragma unroll
        for (int r = 0; r < 7; r++) {
            nl[r] = BIGL;
            if (mk & (1u << r)) {
                int q = pp[r];
                int v =        LAB[q - PW - 1];
                v = min(v,     LAB[q - PW    ]);
                v = min(v,     LAB[q - PW + 1]);
                v = min(v,     LAB[q - 1     ]);
                v = min(v,     LAB[q         ]);
                v = min(v,     LAB[q + 1     ]);
                v = min(v,     LAB[q + PW - 1]);
                v = min(v,     LAB[q + PW    ]);
                v = min(v,     LAB[q + PW + 1]);
                v = LAB[v];        // pointer jump 1 (v is a valid masked padded idx)
                v = LAB[v];        // pointer jump 2
                nl[r] = v;
            }
        }
        __syncwarp();
        bool ch = false;
        #pragma unroll
        for (int r = 0; r < 7; r++) {
            if ((mk & (1u << r)) && nl[r] < LAB[pp[r]]) {
                LAB[pp[r]] = nl[r];            // exclusive owner write
                ch = true;
            }
        }
        if (!__any_sync(0xffffffffu, ch)) break;   // vote = sync point
        __syncwarp();
    }
    __syncwarp();

    // ---- per-component sums (warp-private shared atomics)
    #pragma unroll
    for (int r = 0; r < 7; r++)
        if (mk & (1u << r)) atomicAdd(&PU[LAB[pp[r]]], xv[r]);
    __syncwarp();

    // ---- entropy over roots, warp-reduce, one global atomic per warp
    float h = 0.f;
    const float invB = 1.0f / Bsum;
    #pragma unroll
    for (int r = 0; r < 7; r++) {
        if ((mk & (1u << r)) && LAB[pp[r]] == pp[r]) {
            float pn = PU[pp[r]] * invB;
            h -= pn * logf(pn);
        }
    }
    #pragma unroll
    for (int o = 16; o; o >>= 1) h += __shfl_xor_sync(0xffffffffu, h, o);
    if (lane == 0) atomicAdd(out, h * inv_n);
}

extern "C" void kernel_launch(void* const* d_in, const int* in_sizes, int n_in,
                              void* d_out, int out_size)
{
    const float* dq = (const float*)d_in[0];
    float* out = (float*)d_out;
    const int n = in_sizes[0] / (SEQ * SEQ);     // 128*12 = 1536

    cudaMemsetAsync(out, 0, sizeof(float));
    blob_loss_kernel<<<(n + WPB - 1) / WPB, 256>>>(dq, out, 1.0f / (float)n, n);
}